// round 14
// baseline (speedup 1.0000x reference)
#include <cuda_runtime.h>

#define SEQ 2048
#define DE  1024
#define NH  16
#define DH  64

// Scratch (device globals — no allocation allowed in kernel_launch).
__device__ float g_q[NH * SEQ * DH];
__device__ float g_k[NH * SEQ * DH];
__device__ float g_v[NH * SEQ * DH];
__device__ float g_z[NH * SEQ * DH];

#define GST 68   // gemm smem stride (floats): [k][row] tiles, float4-aligned

// ---------------------------------------------------------------------------
// Kernel 1: QKV projection. R13: smem tiles transposed to [k][row] so the
// inner loop reads are 1 broadcast LDS.128 (A) + 1 contiguous LDS.128 (B)
// instead of 8 scalar LDS -> FFMA issue fraction 67% -> 89%.
// ---------------------------------------------------------------------------
__global__ __launch_bounds__(256) void qkv_kernel(
    const float* __restrict__ x,  const float* __restrict__ wq,
    const float* __restrict__ wk, const float* __restrict__ wv)
{
    __shared__ float As[32 * GST];   // [k][m-row]
    __shared__ float Bs[32 * GST];   // [k][n-row]

    const int mat  = blockIdx.z >> 4;   // 0=Q, 1=K, 2=V
    const int head = blockIdx.z & 15;
    const float* W = (mat == 0 ? wq : (mat == 1 ? wk : wv)) + (size_t)head * DH * DE;
    float*       O = (mat == 0 ? g_q : (mat == 1 ? g_k : g_v)) + (size_t)head * SEQ * DH;

    const int c0 = blockIdx.y * 64;
    const int tx = threadIdx.x, ty = threadIdx.y;
    const int t  = ty * 16 + tx;

    // Loader coords: tile = 64 rows x 32 k = 512 float4; 2 per thread.
    const int lr0 = t >> 3;          // rows lr0, lr0+32
    const int lq  = (t & 7) * 4;     // k offset

    float acc[4][4] = {};

    for (int k0 = 0; k0 < DE; k0 += 32) {
        #pragma unroll
        for (int i = 0; i < 2; i++) {
            int row = lr0 + 32 * i;
            float4 av = *(const float4*)(x + (size_t)(c0 + row) * DE + k0 + lq);
            As[(lq + 0) * GST + row] = av.x;
            As[(lq + 1) * GST + row] = av.y;
            As[(lq + 2) * GST + row] = av.z;
            As[(lq + 3) * GST + row] = av.w;
            float4 bv = *(const float4*)(W + (size_t)row * DE + k0 + lq);
            Bs[(lq + 0) * GST + row] = bv.x;
            Bs[(lq + 1) * GST + row] = bv.y;
            Bs[(lq + 2) * GST + row] = bv.z;
            Bs[(lq + 3) * GST + row] = bv.w;
        }
        __syncthreads();

        #pragma unroll
        for (int kk = 0; kk < 32; kk++) {
            float4 a4 = *(const float4*)(As + kk * GST + ty * 4);
            float4 b4 = *(const float4*)(Bs + kk * GST + tx * 4);
            float a[4] = { a4.x, a4.y, a4.z, a4.w };
            float b[4] = { b4.x, b4.y, b4.z, b4.w };
            #pragma unroll
            for (int i = 0; i < 4; i++)
                #pragma unroll
                for (int j = 0; j < 4; j++)
                    acc[i][j] = fmaf(a[i], b[j], acc[i][j]);
        }
        __syncthreads();
    }

    #pragma unroll
    for (int i = 0; i < 4; i++)
        #pragma unroll
        for (int j = 0; j < 4; j++)
            O[(size_t)(c0 + ty*4 + i) * DH + tx*4 + j] = acc[i][j];
}

// ---------------------------------------------------------------------------
// LPT schedule: bid -> (head, rt); each SM residue class gets ~equal work.
// ---------------------------------------------------------------------------
struct Sched { short m[512]; };

// ---------------------------------------------------------------------------
// Kernel 2: fused causal flash attention (R12 body, unchanged).
// ---------------------------------------------------------------------------
#define FST 68   // smem stride (floats)

__global__ __launch_bounds__(256) void flash_kernel(Sched sched)
{
    extern __shared__ float sm[];
    float* KbT = sm;               // [h][krow]
    float* QtT = sm + 64 * FST;    // [h][qrow]
    float* Vt  = sm + 2 * 64 * FST;// [c][h]
    float* Ps  = sm + 3 * 64 * FST;// [krow][c]

    const int item = sched.m[blockIdx.x];
    const int head = item >> 5;
    const int rt   = item & 31;
    const int c0b  = rt * 64;
    const float* Kh = g_k + (size_t)head * SEQ * DH;
    const float* Qh = g_q + (size_t)head * SEQ * DH;
    const float* Vh = g_v + (size_t)head * SEQ * DH;

    const int tx = threadIdx.x, ty = threadIdx.y;
    const int t  = ty * 16 + tx;
    const float SCL2 = 0.125f * 1.4426950408889634f;  // (1/sqrt(64)) * log2(e)

    #pragma unroll
    for (int i = 0; i < 4; i++) {
        int f = t + 256 * i;
        int row = f >> 4, quad = f & 15;
        float4 v = *(const float4*)(Kh + (size_t)(c0b + row) * DH + quad * 4);
        KbT[(quad*4 + 0) * FST + row] = v.x;
        KbT[(quad*4 + 1) * FST + row] = v.y;
        KbT[(quad*4 + 2) * FST + row] = v.z;
        KbT[(quad*4 + 3) * FST + row] = v.w;
    }

    float accum[4][4] = {};
    float rsum[4] = {0.0f, 0.0f, 0.0f, 0.0f};

    for (int tt = 0; tt <= rt; tt++) {
        const int t0 = tt * 64;
        __syncthreads();

        #pragma unroll
        for (int i = 0; i < 4; i++) {
            int f = t + 256 * i;
            int row = f >> 4, quad = f & 15;
            float4 qv = *(const float4*)(Qh + (size_t)(t0 + row) * DH + quad * 4);
            QtT[(quad*4 + 0) * FST + row] = qv.x;
            QtT[(quad*4 + 1) * FST + row] = qv.y;
            QtT[(quad*4 + 2) * FST + row] = qv.z;
            QtT[(quad*4 + 3) * FST + row] = qv.w;
            float4 vv = *(const float4*)(Vh + (size_t)(t0 + row) * DH + quad * 4);
            *(float4*)(Vt + row * FST + quad * 4) = vv;
        }
        __syncthreads();

        float s[4][4] = {};
        #pragma unroll 8
        for (int h = 0; h < DH; h++) {
            float4 a4 = *(const float4*)(KbT + h * FST + ty * 4);
            float4 b4 = *(const float4*)(QtT + h * FST + tx * 4);
            float a[4] = { a4.x, a4.y, a4.z, a4.w };
            float b[4] = { b4.x, b4.y, b4.z, b4.w };
            #pragma unroll
            for (int i = 0; i < 4; i++)
                #pragma unroll
                for (int j = 0; j < 4; j++)
                    s[i][j] = fmaf(a[i], b[j], s[i][j]);
        }

        #pragma unroll
        for (int i = 0; i < 4; i++) {
            int gr = c0b + ty*4 + i;
            #pragma unroll
            for (int j = 0; j < 4; j++) {
                int gc = t0 + tx*4 + j;
                float sv = (gc > gr) ? -1e30f : s[i][j] * SCL2;
                float p = exp2f(sv);
                s[i][j] = p;
                rsum[i] += p;
            }
        }

        #pragma unroll
        for (int i = 0; i < 4; i++)
            *(float4*)(Ps + (ty*4 + i) * FST + tx*4) =
                make_float4(s[i][0], s[i][1], s[i][2], s[i][3]);
        __syncwarp();

        #pragma unroll 4
        for (int c4 = 0; c4 < 64; c4 += 4) {
            float4 pr[4], vr[4];
            #pragma unroll
            for (int i = 0; i < 4; i++)
                pr[i] = *(const float4*)(Ps + (ty*4 + i) * FST + c4);
            #pragma unroll
            for (int r = 0; r < 4; r++)
                vr[r] = *(const float4*)(Vt + (c4 + r) * FST + tx * 4);
            #pragma unroll
            for (int i = 0; i < 4; i++) {
                float pi[4] = { pr[i].x, pr[i].y, pr[i].z, pr[i].w };
                #pragma unroll
                for (int r = 0; r < 4; r++) {
                    accum[i][0] = fmaf(pi[r], vr[r].x, accum[i][0]);
                    accum[i][1] = fmaf(pi[r], vr[r].y, accum[i][1]);
                    accum[i][2] = fmaf(pi[r], vr[r].z, accum[i][2]);
                    accum[i][3] = fmaf(pi[r], vr[r].w, accum[i][3]);
                }
            }
        }
    }

    float* Zh = g_z + (size_t)head * SEQ * DH;
    #pragma unroll
    for (int i = 0; i < 4; i++) {
        float rs = rsum[i];
        #pragma unroll
        for (int o = 1; o < 16; o <<= 1)
            rs += __shfl_xor_sync(0xffffffffu, rs, o);
        float inv = 1.0f / rs;
        #pragma unroll
        for (int j = 0; j < 4; j++)
            Zh[(size_t)(c0b + ty*4 + i) * DH + tx*4 + j] = accum[i][j] * inv;
    }
}

// ---------------------------------------------------------------------------
// Kernel 3: output projection — same [k][row] vectorization as qkv.
// ---------------------------------------------------------------------------
__global__ __launch_bounds__(256) void oproj_kernel(
    const float* __restrict__ wo, float* __restrict__ out)
{
    __shared__ float As[32 * GST];
    __shared__ float Bs[32 * GST];

    const int e0 = blockIdx.x * 64;
    const int c0 = blockIdx.y * 64;
    const int tx = threadIdx.x, ty = threadIdx.y;
    const int t  = ty * 16 + tx;

    const int lr0 = t >> 3;
    const int lq  = (t & 7) * 4;

    float acc[4][4] = {};

    for (int k0 = 0; k0 < NH * DH; k0 += 32) {
        #pragma unroll
        for (int i = 0; i < 2; i++) {
            int row = lr0 + 32 * i;
            int k = k0 + lq;                 // 4 consecutive k stay in one head
            int a = k >> 6, h = k & 63;
            float4 av = *(const float4*)(g_z + (size_t)a * SEQ * DH + (size_t)(c0 + row) * DH + h);
            As[(lq + 0) * GST + row] = av.x;
            As[(lq + 1) * GST + row] = av.y;
            As[(lq + 2) * GST + row] = av.z;
            As[(lq + 3) * GST + row] = av.w;
            float4 bv = *(const float4*)(wo + (size_t)a * DE * DH + (size_t)(e0 + row) * DH + h);
            Bs[(lq + 0) * GST + row] = bv.x;
            Bs[(lq + 1) * GST + row] = bv.y;
            Bs[(lq + 2) * GST + row] = bv.z;
            Bs[(lq + 3) * GST + row] = bv.w;
        }
        __syncthreads();

        #pragma unroll
        for (int kk = 0; kk < 32; kk++) {
            float4 a4 = *(const float4*)(As + kk * GST + ty * 4);
            float4 b4 = *(const float4*)(Bs + kk * GST + tx * 4);
            float a[4] = { a4.x, a4.y, a4.z, a4.w };
            float b[4] = { b4.x, b4.y, b4.z, b4.w };
            #pragma unroll
            for (int i = 0; i < 4; i++)
                #pragma unroll
                for (int j = 0; j < 4; j++)
                    acc[i][j] = fmaf(a[i], b[j], acc[i][j]);
        }
        __syncthreads();
    }

    #pragma unroll
    for (int i = 0; i < 4; i++)
        #pragma unroll
        for (int j = 0; j < 4; j++)
            out[(size_t)(c0 + ty*4 + i) * DE + e0 + tx*4 + j] = acc[i][j];
}

// ---------------------------------------------------------------------------
extern "C" void kernel_launch(void* const* d_in, const int* in_sizes, int n_in,
                              void* d_out, int out_size)
{
    const float* x  = (const float*)d_in[0];
    const float* wq = (const float*)d_in[1];
    const float* wk = (const float*)d_in[2];
    const float* wv = (const float*)d_in[3];
    const float* wo = (const float*)d_in[4];
    float* out = (float*)d_out;

    dim3 blk(16, 16);

    qkv_kernel<<<dim3(1, SEQ / 64, 48), blk>>>(x, wq, wk, wv);

    // LPT schedule over SM residue classes (bid % 148 shares an SM).
    Sched sched;
    {
        int load[148], cnt[148];
        for (int r = 0; r < 148; r++) { load[r] = 0; cnt[r] = 0; }
        for (int s = 32; s >= 1; s--) {
            for (int head = 0; head < NH; head++) {
                int best = -1;
                for (int r = 0; r < 148; r++) {
                    int slots = (r < 68) ? 4 : 3;
                    if (cnt[r] < slots && (best < 0 || load[r] < load[best]))
                        best = r;
                }
                int bid = best + 148 * cnt[best];
                cnt[best]++;
                load[best] += s;
                sched.m[bid] = (short)(head * 32 + (s - 1));
            }
        }
    }

    const size_t shm = 4 * 64 * FST * sizeof(float);  // 69632 B
    cudaFuncSetAttribute(flash_kernel, cudaFuncAttributeMaxDynamicSharedMemorySize, (int)shm);
    flash_kernel<<<512, blk, shm>>>(sched);

    oproj_kernel<<<dim3(DE / 64, SEQ / 64), blk>>>(wo, out);
}

// round 15
// speedup vs baseline: 1.1015x; 1.1015x over previous
#include <cuda_runtime.h>

#define SEQ 2048
#define DE  1024
#define NH  16
#define DH  64

// Scratch (device globals — no allocation allowed in kernel_launch).
__device__ float g_q[NH * SEQ * DH];
__device__ float g_k[NH * SEQ * DH];
__device__ float g_v[NH * SEQ * DH];
__device__ float g_z[NH * SEQ * DH];

// ---------------------------------------------------------------------------
// Kernel 1: QKV projection — R1 body (proven 352us; ptxas pipelines the
// scalar LDS across k-steps; do NOT "vectorize" this, see R13 regression).
// ---------------------------------------------------------------------------
__global__ __launch_bounds__(256) void qkv_kernel(
    const float* __restrict__ x,  const float* __restrict__ wq,
    const float* __restrict__ wk, const float* __restrict__ wv)
{
    __shared__ float As[64][33];
    __shared__ float Bs[64][33];

    const int mat  = blockIdx.z >> 4;   // 0=Q, 1=K, 2=V
    const int head = blockIdx.z & 15;
    const float* W = (mat == 0 ? wq : (mat == 1 ? wk : wv)) + (size_t)head * DH * DE;
    float*       O = (mat == 0 ? g_q : (mat == 1 ? g_k : g_v)) + (size_t)head * SEQ * DH;

    const int c0 = blockIdx.y * 64;
    const int tx = threadIdx.x, ty = threadIdx.y;
    const int t  = ty * 16 + tx;

    float acc[4][4] = {};

    for (int k0 = 0; k0 < DE; k0 += 32) {
        #pragma unroll
        for (int i = 0; i < 2; i++) {
            int f = t + 256 * i;
            int row = f >> 3, quad = f & 7;
            float4 av = *(const float4*)(x + (size_t)(c0 + row) * DE + k0 + quad * 4);
            As[row][quad*4+0] = av.x; As[row][quad*4+1] = av.y;
            As[row][quad*4+2] = av.z; As[row][quad*4+3] = av.w;
            float4 bv = *(const float4*)(W + (size_t)row * DE + k0 + quad * 4);
            Bs[row][quad*4+0] = bv.x; Bs[row][quad*4+1] = bv.y;
            Bs[row][quad*4+2] = bv.z; Bs[row][quad*4+3] = bv.w;
        }
        __syncthreads();

        #pragma unroll
        for (int kk = 0; kk < 32; kk++) {
            float a[4], b[4];
            #pragma unroll
            for (int i = 0; i < 4; i++) a[i] = As[ty*4 + i][kk];
            #pragma unroll
            for (int j = 0; j < 4; j++) b[j] = Bs[tx*4 + j][kk];
            #pragma unroll
            for (int i = 0; i < 4; i++)
                #pragma unroll
                for (int j = 0; j < 4; j++)
                    acc[i][j] = fmaf(a[i], b[j], acc[i][j]);
        }
        __syncthreads();
    }

    #pragma unroll
    for (int i = 0; i < 4; i++)
        #pragma unroll
        for (int j = 0; j < 4; j++)
            O[(size_t)(c0 + ty*4 + i) * DH + tx*4 + j] = acc[i][j];
}

// ---------------------------------------------------------------------------
// LPT schedule: bid -> (head, rt); each SM residue class gets ~equal work.
// ---------------------------------------------------------------------------
struct Sched { short m[512]; };

// ---------------------------------------------------------------------------
// Kernel 2: fused causal flash attention (R12 body + smem reduction).
// R14: Ps ALIASES QtT (QtT is dead after the QK loop; one extra barrier
// between last QK read and first Ps write makes the reuse safe).
// smem 69632 -> 52224 B => 4 blocks/SM (32 warps, +33% latency hiding).
// ---------------------------------------------------------------------------
#define FST 68   // smem stride (floats)

__global__ __launch_bounds__(256, 4) void flash_kernel(Sched sched)
{
    extern __shared__ float sm[];
    float* KbT = sm;               // [h][krow]
    float* QtT = sm + 64 * FST;    // [h][qrow]  (reused as Ps after QK)
    float* Vt  = sm + 2 * 64 * FST;// [c][h]
    float* Ps  = QtT;              // [krow][c]  alias

    const int item = sched.m[blockIdx.x];
    const int head = item >> 5;
    const int rt   = item & 31;
    const int c0b  = rt * 64;
    const float* Kh = g_k + (size_t)head * SEQ * DH;
    const float* Qh = g_q + (size_t)head * SEQ * DH;
    const float* Vh = g_v + (size_t)head * SEQ * DH;

    const int tx = threadIdx.x, ty = threadIdx.y;
    const int t  = ty * 16 + tx;
    const float SCL2 = 0.125f * 1.4426950408889634f;  // (1/sqrt(64)) * log2(e)

    // Load this block's 64 K-rows once, transposed.
    #pragma unroll
    for (int i = 0; i < 4; i++) {
        int f = t + 256 * i;
        int row = f >> 4, quad = f & 15;
        float4 v = *(const float4*)(Kh + (size_t)(c0b + row) * DH + quad * 4);
        KbT[(quad*4 + 0) * FST + row] = v.x;
        KbT[(quad*4 + 1) * FST + row] = v.y;
        KbT[(quad*4 + 2) * FST + row] = v.z;
        KbT[(quad*4 + 3) * FST + row] = v.w;
    }

    float accum[4][4] = {};
    float rsum[4] = {0.0f, 0.0f, 0.0f, 0.0f};   // per-thread partial row sums

    for (int tt = 0; tt <= rt; tt++) {
        const int t0 = tt * 64;
        __syncthreads();  // prev iter done with Ps(=QtT)/Vt (KbT visible at tt=0)

        #pragma unroll
        for (int i = 0; i < 4; i++) {
            int f = t + 256 * i;
            int row = f >> 4, quad = f & 15;
            float4 qv = *(const float4*)(Qh + (size_t)(t0 + row) * DH + quad * 4);
            QtT[(quad*4 + 0) * FST + row] = qv.x;
            QtT[(quad*4 + 1) * FST + row] = qv.y;
            QtT[(quad*4 + 2) * FST + row] = qv.z;
            QtT[(quad*4 + 3) * FST + row] = qv.w;
            float4 vv = *(const float4*)(Vh + (size_t)(t0 + row) * DH + quad * 4);
            *(float4*)(Vt + row * FST + quad * 4) = vv;
        }
        __syncthreads();

        // S = K_rows @ Qt^T : vectorized operand reads.
        float s[4][4] = {};
        #pragma unroll 8
        for (int h = 0; h < DH; h++) {
            float4 a4 = *(const float4*)(KbT + h * FST + ty * 4);
            float4 b4 = *(const float4*)(QtT + h * FST + tx * 4);
            float a[4] = { a4.x, a4.y, a4.z, a4.w };
            float b[4] = { b4.x, b4.y, b4.z, b4.w };
            #pragma unroll
            for (int i = 0; i < 4; i++)
                #pragma unroll
                for (int j = 0; j < 4; j++)
                    s[i][j] = fmaf(a[i], b[j], s[i][j]);
        }

        // Mask + scale + direct exp2 (max-free; register-only, overlaps
        // barrier skew below).
        #pragma unroll
        for (int i = 0; i < 4; i++) {
            int gr = c0b + ty*4 + i;
            #pragma unroll
            for (int j = 0; j < 4; j++) {
                int gc = t0 + tx*4 + j;
                float sv = (gc > gr) ? -1e30f : s[i][j] * SCL2;
                float p = exp2f(sv);
                s[i][j] = p;
                rsum[i] += p;
            }
        }

        __syncthreads();  // all QK reads of QtT complete before Ps overwrite

        // Share P tile (rows ty*4+i are warp-private for the PV reads).
        #pragma unroll
        for (int i = 0; i < 4; i++)
            *(float4*)(Ps + (ty*4 + i) * FST + tx*4) =
                make_float4(s[i][0], s[i][1], s[i][2], s[i][3]);
        __syncwarp();

        // O += P @ V : fully vectorized, 4 columns per step.
        #pragma unroll 4
        for (int c4 = 0; c4 < 64; c4 += 4) {
            float4 pr[4], vr[4];
            #pragma unroll
            for (int i = 0; i < 4; i++)
                pr[i] = *(const float4*)(Ps + (ty*4 + i) * FST + c4);
            #pragma unroll
            for (int r = 0; r < 4; r++)
                vr[r] = *(const float4*)(Vt + (c4 + r) * FST + tx * 4);
            #pragma unroll
            for (int i = 0; i < 4; i++) {
                float pi[4] = { pr[i].x, pr[i].y, pr[i].z, pr[i].w };
                #pragma unroll
                for (int r = 0; r < 4; r++) {
                    accum[i][0] = fmaf(pi[r], vr[r].x, accum[i][0]);
                    accum[i][1] = fmaf(pi[r], vr[r].y, accum[i][1]);
                    accum[i][2] = fmaf(pi[r], vr[r].z, accum[i][2]);
                    accum[i][3] = fmaf(pi[r], vr[r].w, accum[i][3]);
                }
            }
        }
    }

    // Final row-sum reduction + normalize.
    float* Zh = g_z + (size_t)head * SEQ * DH;
    #pragma unroll
    for (int i = 0; i < 4; i++) {
        float rs = rsum[i];
        #pragma unroll
        for (int o = 1; o < 16; o <<= 1)
            rs += __shfl_xor_sync(0xffffffffu, rs, o);
        float inv = 1.0f / rs;
        #pragma unroll
        for (int j = 0; j < 4; j++)
            Zh[(size_t)(c0b + ty*4 + i) * DH + tx*4 + j] = accum[i][j] * inv;
    }
}

// ---------------------------------------------------------------------------
// Kernel 3: output projection — R1 body (proven).
// ---------------------------------------------------------------------------
__global__ __launch_bounds__(256) void oproj_kernel(
    const float* __restrict__ wo, float* __restrict__ out)
{
    __shared__ float As[64][33];
    __shared__ float Bs[64][33];

    const int e0 = blockIdx.x * 64;
    const int c0 = blockIdx.y * 64;
    const int tx = threadIdx.x, ty = threadIdx.y;
    const int t  = ty * 16 + tx;

    float acc[4][4] = {};

    for (int k0 = 0; k0 < NH * DH; k0 += 32) {
        #pragma unroll
        for (int i = 0; i < 2; i++) {
            int f = t + 256 * i;
            int row = f >> 3, quad = f & 7;
            int k = k0 + quad * 4;
            int a = k >> 6, h = k & 63;
            float4 av = *(const float4*)(g_z + (size_t)a * SEQ * DH + (size_t)(c0 + row) * DH + h);
            As[row][quad*4+0] = av.x; As[row][quad*4+1] = av.y;
            As[row][quad*4+2] = av.z; As[row][quad*4+3] = av.w;
            float4 bv = *(const float4*)(wo + (size_t)a * DE * DH + (size_t)(e0 + row) * DH + h);
            Bs[row][quad*4+0] = bv.x; Bs[row][quad*4+1] = bv.y;
            Bs[row][quad*4+2] = bv.z; Bs[row][quad*4+3] = bv.w;
        }
        __syncthreads();

        #pragma unroll
        for (int kk = 0; kk < 32; kk++) {
            float a[4], b[4];
            #pragma unroll
            for (int i = 0; i < 4; i++) a[i] = As[ty*4 + i][kk];
            #pragma unroll
            for (int j = 0; j < 4; j++) b[j] = Bs[tx*4 + j][kk];
            #pragma unroll
            for (int i = 0; i < 4; i++)
                #pragma unroll
                for (int j = 0; j < 4; j++)
                    acc[i][j] = fmaf(a[i], b[j], acc[i][j]);
        }
        __syncthreads();
    }

    #pragma unroll
    for (int i = 0; i < 4; i++)
        #pragma unroll
        for (int j = 0; j < 4; j++)
            out[(size_t)(c0 + ty*4 + i) * DE + e0 + tx*4 + j] = acc[i][j];
}

// ---------------------------------------------------------------------------
extern "C" void kernel_launch(void* const* d_in, const int* in_sizes, int n_in,
                              void* d_out, int out_size)
{
    const float* x  = (const float*)d_in[0];
    const float* wq = (const float*)d_in[1];
    const float* wk = (const float*)d_in[2];
    const float* wv = (const float*)d_in[3];
    const float* wo = (const float*)d_in[4];
    float* out = (float*)d_out;

    dim3 blk(16, 16);

    qkv_kernel<<<dim3(1, SEQ / 64, 48), blk>>>(x, wq, wk, wv);

    // LPT schedule over SM residue classes (bid % 148 shares an SM).
    Sched sched;
    {
        int load[148], cnt[148];
        for (int r = 0; r < 148; r++) { load[r] = 0; cnt[r] = 0; }
        for (int s = 32; s >= 1; s--) {
            for (int head = 0; head < NH; head++) {
                int best = -1;
                for (int r = 0; r < 148; r++) {
                    int slots = (r < 68) ? 4 : 3;
                    if (cnt[r] < slots && (best < 0 || load[r] < load[best]))
                        best = r;
                }
                int bid = best + 148 * cnt[best];
                cnt[best]++;
                load[best] += s;
                sched.m[bid] = (short)(head * 32 + (s - 1));
            }
        }
    }

    const size_t shm = 3 * 64 * FST * sizeof(float);  // 52224 B -> 4 blocks/SM
    cudaFuncSetAttribute(flash_kernel, cudaFuncAttributeMaxDynamicSharedMemorySize, (int)shm);
    flash_kernel<<<512, blk, shm>>>(sched);

    oproj_kernel<<<dim3(DE / 64, SEQ / 64), blk>>>(wo, out);
}

// round 16
// speedup vs baseline: 1.1233x; 1.0198x over previous
#include <cuda_runtime.h>

#define SEQ 2048
#define DE  1024
#define NH  16
#define DH  64

// Scratch (device globals — no allocation allowed in kernel_launch).
__device__ float g_q[NH * SEQ * DH];
__device__ float g_k[NH * SEQ * DH];
__device__ float g_v[NH * SEQ * DH];
__device__ float g_z[NH * SEQ * DH];
__device__ int   g_cnt[NH];          // per-head qkv completion counters

#define FST 68   // flash smem stride (floats)

// ---------------------------------------------------------------------------
// Fused kernel: bids 0..1535 = QKV projection (producer, head-major);
//               bids 1536..2047 = flash attention (consumer, gated per head).
// Producers never wait; all producer bids precede consumer bids, so freed
// slots always go to the lowest pending bid -> no deadlock.
// ---------------------------------------------------------------------------
__global__ __launch_bounds__(256, 3) void fused_kernel(
    const float* __restrict__ x,  const float* __restrict__ wq,
    const float* __restrict__ wk, const float* __restrict__ wv)
{
    extern __shared__ float sm[];

    const int bid = blockIdx.x;
    const int tx = threadIdx.x, ty = threadIdx.y;
    const int t  = ty * 16 + tx;

    if (bid < 1536) {
        // =================== QKV role (R1 body, proven 352us) ===============
        const int head = bid / 96;
        const int sub  = bid % 96;
        const int mat  = sub >> 5;          // 0=Q, 1=K, 2=V
        const int c0   = (sub & 31) * 64;

        float (*As)[33] = (float(*)[33])sm;
        float (*Bs)[33] = (float(*)[33])(sm + 64 * 33);

        const float* W = (mat == 0 ? wq : (mat == 1 ? wk : wv)) + (size_t)head * DH * DE;
        float*       O = (mat == 0 ? g_q : (mat == 1 ? g_k : g_v)) + (size_t)head * SEQ * DH;

        float acc[4][4] = {};

        for (int k0 = 0; k0 < DE; k0 += 32) {
            #pragma unroll
            for (int i = 0; i < 2; i++) {
                int f = t + 256 * i;
                int row = f >> 3, quad = f & 7;
                float4 av = *(const float4*)(x + (size_t)(c0 + row) * DE + k0 + quad * 4);
                As[row][quad*4+0] = av.x; As[row][quad*4+1] = av.y;
                As[row][quad*4+2] = av.z; As[row][quad*4+3] = av.w;
                float4 bv = *(const float4*)(W + (size_t)row * DE + k0 + quad * 4);
                Bs[row][quad*4+0] = bv.x; Bs[row][quad*4+1] = bv.y;
                Bs[row][quad*4+2] = bv.z; Bs[row][quad*4+3] = bv.w;
            }
            __syncthreads();

            #pragma unroll
            for (int kk = 0; kk < 32; kk++) {
                float a[4], b[4];
                #pragma unroll
                for (int i = 0; i < 4; i++) a[i] = As[ty*4 + i][kk];
                #pragma unroll
                for (int j = 0; j < 4; j++) b[j] = Bs[tx*4 + j][kk];
                #pragma unroll
                for (int i = 0; i < 4; i++)
                    #pragma unroll
                    for (int j = 0; j < 4; j++)
                        acc[i][j] = fmaf(a[i], b[j], acc[i][j]);
            }
            __syncthreads();
        }

        #pragma unroll
        for (int i = 0; i < 4; i++)
            #pragma unroll
            for (int j = 0; j < 4; j++)
                O[(size_t)(c0 + ty*4 + i) * DH + tx*4 + j] = acc[i][j];

        // Release: my stores visible, then count this block.
        __threadfence();
        __syncthreads();
        if (t == 0) atomicAdd(&g_cnt[head], 1);

    } else {
        // =================== Flash role (R12 body, proven) ==================
        const int fid  = bid - 1536;
        const int head = fid >> 5;                 // heads ascending
        const int rt   = 31 - (fid & 31);          // sizes descending in head
        const int c0b  = rt * 64;

        // Gate: wait until this head's 96 qkv blocks are done.
        if (t == 0) {
            volatile int* c = &g_cnt[head];
            while (*c < 96) __nanosleep(200);
            __threadfence();
        }
        __syncthreads();

        float* KbT = sm;               // [h][krow]
        float* QtT = sm + 64 * FST;    // [h][qrow]
        float* Vt  = sm + 2 * 64 * FST;// [c][h]
        float* Ps  = sm + 3 * 64 * FST;// [krow][c]

        const float* Kh = g_k + (size_t)head * SEQ * DH;
        const float* Qh = g_q + (size_t)head * SEQ * DH;
        const float* Vh = g_v + (size_t)head * SEQ * DH;
        const float SCL2 = 0.125f * 1.4426950408889634f;  // (1/sqrt(64))*log2(e)

        #pragma unroll
        for (int i = 0; i < 4; i++) {
            int f = t + 256 * i;
            int row = f >> 4, quad = f & 15;
            float4 v = *(const float4*)(Kh + (size_t)(c0b + row) * DH + quad * 4);
            KbT[(quad*4 + 0) * FST + row] = v.x;
            KbT[(quad*4 + 1) * FST + row] = v.y;
            KbT[(quad*4 + 2) * FST + row] = v.z;
            KbT[(quad*4 + 3) * FST + row] = v.w;
        }

        float accum[4][4] = {};
        float rsum[4] = {0.0f, 0.0f, 0.0f, 0.0f};

        for (int tt = 0; tt <= rt; tt++) {
            const int t0 = tt * 64;
            __syncthreads();

            #pragma unroll
            for (int i = 0; i < 4; i++) {
                int f = t + 256 * i;
                int row = f >> 4, quad = f & 15;
                float4 qv = *(const float4*)(Qh + (size_t)(t0 + row) * DH + quad * 4);
                QtT[(quad*4 + 0) * FST + row] = qv.x;
                QtT[(quad*4 + 1) * FST + row] = qv.y;
                QtT[(quad*4 + 2) * FST + row] = qv.z;
                QtT[(quad*4 + 3) * FST + row] = qv.w;
                float4 vv = *(const float4*)(Vh + (size_t)(t0 + row) * DH + quad * 4);
                *(float4*)(Vt + row * FST + quad * 4) = vv;
            }
            __syncthreads();

            float s[4][4] = {};
            #pragma unroll 8
            for (int h = 0; h < DH; h++) {
                float4 a4 = *(const float4*)(KbT + h * FST + ty * 4);
                float4 b4 = *(const float4*)(QtT + h * FST + tx * 4);
                float a[4] = { a4.x, a4.y, a4.z, a4.w };
                float b[4] = { b4.x, b4.y, b4.z, b4.w };
                #pragma unroll
                for (int i = 0; i < 4; i++)
                    #pragma unroll
                    for (int j = 0; j < 4; j++)
                        s[i][j] = fmaf(a[i], b[j], s[i][j]);
            }

            #pragma unroll
            for (int i = 0; i < 4; i++) {
                int gr = c0b + ty*4 + i;
                #pragma unroll
                for (int j = 0; j < 4; j++) {
                    int gc = t0 + tx*4 + j;
                    float sv = (gc > gr) ? -1e30f : s[i][j] * SCL2;
                    float p = exp2f(sv);
                    s[i][j] = p;
                    rsum[i] += p;
                }
            }

            #pragma unroll
            for (int i = 0; i < 4; i++)
                *(float4*)(Ps + (ty*4 + i) * FST + tx*4) =
                    make_float4(s[i][0], s[i][1], s[i][2], s[i][3]);
            __syncwarp();

            #pragma unroll 4
            for (int c4 = 0; c4 < 64; c4 += 4) {
                float4 pr[4], vr[4];
                #pragma unroll
                for (int i = 0; i < 4; i++)
                    pr[i] = *(const float4*)(Ps + (ty*4 + i) * FST + c4);
                #pragma unroll
                for (int r = 0; r < 4; r++)
                    vr[r] = *(const float4*)(Vt + (c4 + r) * FST + tx * 4);
                #pragma unroll
                for (int i = 0; i < 4; i++) {
                    float pi[4] = { pr[i].x, pr[i].y, pr[i].z, pr[i].w };
                    #pragma unroll
                    for (int r = 0; r < 4; r++) {
                        accum[i][0] = fmaf(pi[r], vr[r].x, accum[i][0]);
                        accum[i][1] = fmaf(pi[r], vr[r].y, accum[i][1]);
                        accum[i][2] = fmaf(pi[r], vr[r].z, accum[i][2]);
                        accum[i][3] = fmaf(pi[r], vr[r].w, accum[i][3]);
                    }
                }
            }
        }

        float* Zh = g_z + (size_t)head * SEQ * DH;
        #pragma unroll
        for (int i = 0; i < 4; i++) {
            float rs = rsum[i];
            #pragma unroll
            for (int o = 1; o < 16; o <<= 1)
                rs += __shfl_xor_sync(0xffffffffu, rs, o);
            float inv = 1.0f / rs;
            #pragma unroll
            for (int j = 0; j < 4; j++)
                Zh[(size_t)(c0b + ty*4 + i) * DH + tx*4 + j] = accum[i][j] * inv;
        }
    }
}

// ---------------------------------------------------------------------------
// Output projection — R1 body (at FFMA roofline; unchanged).
// ---------------------------------------------------------------------------
__global__ __launch_bounds__(256) void oproj_kernel(
    const float* __restrict__ wo, float* __restrict__ out)
{
    __shared__ float As[64][33];
    __shared__ float Bs[64][33];

    const int e0 = blockIdx.x * 64;
    const int c0 = blockIdx.y * 64;
    const int tx = threadIdx.x, ty = threadIdx.y;
    const int t  = ty * 16 + tx;

    float acc[4][4] = {};

    for (int k0 = 0; k0 < NH * DH; k0 += 32) {
        #pragma unroll
        for (int i = 0; i < 2; i++) {
            int f = t + 256 * i;
            int row = f >> 3, quad = f & 7;
            int k = k0 + quad * 4;
            int a = k >> 6, h = k & 63;
            float4 av = *(const float4*)(g_z + (size_t)a * SEQ * DH + (size_t)(c0 + row) * DH + h);
            As[row][quad*4+0] = av.x; As[row][quad*4+1] = av.y;
            As[row][quad*4+2] = av.z; As[row][quad*4+3] = av.w;
            float4 bv = *(const float4*)(wo + (size_t)a * DE * DH + (size_t)(e0 + row) * DH + h);
            Bs[row][quad*4+0] = bv.x; Bs[row][quad*4+1] = bv.y;
            Bs[row][quad*4+2] = bv.z; Bs[row][quad*4+3] = bv.w;
        }
        __syncthreads();

        #pragma unroll
        for (int kk = 0; kk < 32; kk++) {
            float a[4], b[4];
            #pragma unroll
            for (int i = 0; i < 4; i++) a[i] = As[ty*4 + i][kk];
            #pragma unroll
            for (int j = 0; j < 4; j++) b[j] = Bs[tx*4 + j][kk];
            #pragma unroll
            for (int i = 0; i < 4; i++)
                #pragma unroll
                for (int j = 0; j < 4; j++)
                    acc[i][j] = fmaf(a[i], b[j], acc[i][j]);
        }
        __syncthreads();
    }

    #pragma unroll
    for (int i = 0; i < 4; i++)
        #pragma unroll
        for (int j = 0; j < 4; j++)
            out[(size_t)(c0 + ty*4 + i) * DE + e0 + tx*4 + j] = acc[i][j];
}

// ---------------------------------------------------------------------------
extern "C" void kernel_launch(void* const* d_in, const int* in_sizes, int n_in,
                              void* d_out, int out_size)
{
    const float* x  = (const float*)d_in[0];
    const float* wq = (const float*)d_in[1];
    const float* wk = (const float*)d_in[2];
    const float* wv = (const float*)d_in[3];
    const float* wo = (const float*)d_in[4];
    float* out = (float*)d_out;

    // Reset per-head counters (captured as a memset node; deterministic replay).
    void* cptr = nullptr;
    cudaGetSymbolAddress(&cptr, g_cnt);
    cudaMemsetAsync(cptr, 0, sizeof(int) * NH);

    const size_t shm = 4 * 64 * FST * sizeof(float);  // 69632 B
    cudaFuncSetAttribute(fused_kernel, cudaFuncAttributeMaxDynamicSharedMemorySize, (int)shm);

    dim3 blk(16, 16);
    fused_kernel<<<2048, blk, shm>>>(x, wq, wk, wv);

    oproj_kernel<<<dim3(DE / 64, SEQ / 64), blk>>>(wo, out);
}

// round 17
// speedup vs baseline: 1.1535x; 1.0269x over previous
#include <cuda_runtime.h>

#define SEQ 2048
#define DE  1024
#define NH  16
#define DH  64

// Scratch (device globals — no allocation allowed in kernel_launch).
__device__ float g_q[NH * SEQ * DH];
__device__ float g_k[NH * SEQ * DH];
__device__ float g_v[NH * SEQ * DH];
__device__ float g_z[NH * SEQ * DH];

// ---------------------------------------------------------------------------
// Kernel 1: QKV projection — R1 body (proven 352us).
// ---------------------------------------------------------------------------
__global__ __launch_bounds__(256) void qkv_kernel(
    const float* __restrict__ x,  const float* __restrict__ wq,
    const float* __restrict__ wk, const float* __restrict__ wv)
{
    __shared__ float As[64][33];
    __shared__ float Bs[64][33];

    const int mat  = blockIdx.z >> 4;   // 0=Q, 1=K, 2=V
    const int head = blockIdx.z & 15;
    const float* W = (mat == 0 ? wq : (mat == 1 ? wk : wv)) + (size_t)head * DH * DE;
    float*       O = (mat == 0 ? g_q : (mat == 1 ? g_k : g_v)) + (size_t)head * SEQ * DH;

    const int c0 = blockIdx.y * 64;
    const int tx = threadIdx.x, ty = threadIdx.y;
    const int t  = ty * 16 + tx;

    float acc[4][4] = {};

    for (int k0 = 0; k0 < DE; k0 += 32) {
        #pragma unroll
        for (int i = 0; i < 2; i++) {
            int f = t + 256 * i;
            int row = f >> 3, quad = f & 7;
            float4 av = *(const float4*)(x + (size_t)(c0 + row) * DE + k0 + quad * 4);
            As[row][quad*4+0] = av.x; As[row][quad*4+1] = av.y;
            As[row][quad*4+2] = av.z; As[row][quad*4+3] = av.w;
            float4 bv = *(const float4*)(W + (size_t)row * DE + k0 + quad * 4);
            Bs[row][quad*4+0] = bv.x; Bs[row][quad*4+1] = bv.y;
            Bs[row][quad*4+2] = bv.z; Bs[row][quad*4+3] = bv.w;
        }
        __syncthreads();

        #pragma unroll
        for (int kk = 0; kk < 32; kk++) {
            float a[4], b[4];
            #pragma unroll
            for (int i = 0; i < 4; i++) a[i] = As[ty*4 + i][kk];
            #pragma unroll
            for (int j = 0; j < 4; j++) b[j] = Bs[tx*4 + j][kk];
            #pragma unroll
            for (int i = 0; i < 4; i++)
                #pragma unroll
                for (int j = 0; j < 4; j++)
                    acc[i][j] = fmaf(a[i], b[j], acc[i][j]);
        }
        __syncthreads();
    }

    #pragma unroll
    for (int i = 0; i < 4; i++)
        #pragma unroll
        for (int j = 0; j < 4; j++)
            O[(size_t)(c0 + ty*4 + i) * DH + tx*4 + j] = acc[i][j];
}

// ---------------------------------------------------------------------------
// LPT schedule: bid -> (head, rt); each SM residue class gets ~equal work.
// ---------------------------------------------------------------------------
struct Sched { short m[512]; };

// ---------------------------------------------------------------------------
// Kernel 2: fused causal flash attention (R12 body — 815us best config).
// ---------------------------------------------------------------------------
#define FST 68   // smem stride (floats)

__global__ __launch_bounds__(256) void flash_kernel(Sched sched)
{
    extern __shared__ float sm[];
    float* KbT = sm;               // [h][krow]
    float* QtT = sm + 64 * FST;    // [h][qrow]
    float* Vt  = sm + 2 * 64 * FST;// [c][h]
    float* Ps  = sm + 3 * 64 * FST;// [krow][c]

    const int item = sched.m[blockIdx.x];
    const int head = item >> 5;
    const int rt   = item & 31;
    const int c0b  = rt * 64;
    const float* Kh = g_k + (size_t)head * SEQ * DH;
    const float* Qh = g_q + (size_t)head * SEQ * DH;
    const float* Vh = g_v + (size_t)head * SEQ * DH;

    const int tx = threadIdx.x, ty = threadIdx.y;
    const int t  = ty * 16 + tx;
    const float SCL2 = 0.125f * 1.4426950408889634f;  // (1/sqrt(64)) * log2(e)

    #pragma unroll
    for (int i = 0; i < 4; i++) {
        int f = t + 256 * i;
        int row = f >> 4, quad = f & 15;
        float4 v = *(const float4*)(Kh + (size_t)(c0b + row) * DH + quad * 4);
        KbT[(quad*4 + 0) * FST + row] = v.x;
        KbT[(quad*4 + 1) * FST + row] = v.y;
        KbT[(quad*4 + 2) * FST + row] = v.z;
        KbT[(quad*4 + 3) * FST + row] = v.w;
    }

    float accum[4][4] = {};
    float rsum[4] = {0.0f, 0.0f, 0.0f, 0.0f};

    for (int tt = 0; tt <= rt; tt++) {
        const int t0 = tt * 64;
        __syncthreads();

        #pragma unroll
        for (int i = 0; i < 4; i++) {
            int f = t + 256 * i;
            int row = f >> 4, quad = f & 15;
            float4 qv = *(const float4*)(Qh + (size_t)(t0 + row) * DH + quad * 4);
            QtT[(quad*4 + 0) * FST + row] = qv.x;
            QtT[(quad*4 + 1) * FST + row] = qv.y;
            QtT[(quad*4 + 2) * FST + row] = qv.z;
            QtT[(quad*4 + 3) * FST + row] = qv.w;
            float4 vv = *(const float4*)(Vh + (size_t)(t0 + row) * DH + quad * 4);
            *(float4*)(Vt + row * FST + quad * 4) = vv;
        }
        __syncthreads();

        float s[4][4] = {};
        #pragma unroll 8
        for (int h = 0; h < DH; h++) {
            float4 a4 = *(const float4*)(KbT + h * FST + ty * 4);
            float4 b4 = *(const float4*)(QtT + h * FST + tx * 4);
            float a[4] = { a4.x, a4.y, a4.z, a4.w };
            float b[4] = { b4.x, b4.y, b4.z, b4.w };
            #pragma unroll
            for (int i = 0; i < 4; i++)
                #pragma unroll
                for (int j = 0; j < 4; j++)
                    s[i][j] = fmaf(a[i], b[j], s[i][j]);
        }

        #pragma unroll
        for (int i = 0; i < 4; i++) {
            int gr = c0b + ty*4 + i;
            #pragma unroll
            for (int j = 0; j < 4; j++) {
                int gc = t0 + tx*4 + j;
                float sv = (gc > gr) ? -1e30f : s[i][j] * SCL2;
                float p = exp2f(sv);
                s[i][j] = p;
                rsum[i] += p;
            }
        }

        #pragma unroll
        for (int i = 0; i < 4; i++)
            *(float4*)(Ps + (ty*4 + i) * FST + tx*4) =
                make_float4(s[i][0], s[i][1], s[i][2], s[i][3]);
        __syncwarp();

        #pragma unroll 4
        for (int c4 = 0; c4 < 64; c4 += 4) {
            float4 pr[4], vr[4];
            #pragma unroll
            for (int i = 0; i < 4; i++)
                pr[i] = *(const float4*)(Ps + (ty*4 + i) * FST + c4);
            #pragma unroll
            for (int r = 0; r < 4; r++)
                vr[r] = *(const float4*)(Vt + (c4 + r) * FST + tx * 4);
            #pragma unroll
            for (int i = 0; i < 4; i++) {
                float pi[4] = { pr[i].x, pr[i].y, pr[i].z, pr[i].w };
                #pragma unroll
                for (int r = 0; r < 4; r++) {
                    accum[i][0] = fmaf(pi[r], vr[r].x, accum[i][0]);
                    accum[i][1] = fmaf(pi[r], vr[r].y, accum[i][1]);
                    accum[i][2] = fmaf(pi[r], vr[r].z, accum[i][2]);
                    accum[i][3] = fmaf(pi[r], vr[r].w, accum[i][3]);
                }
            }
        }
    }

    float* Zh = g_z + (size_t)head * SEQ * DH;
    #pragma unroll
    for (int i = 0; i < 4; i++) {
        float rs = rsum[i];
        #pragma unroll
        for (int o = 1; o < 16; o <<= 1)
            rs += __shfl_xor_sync(0xffffffffu, rs, o);
        float inv = 1.0f / rs;
        #pragma unroll
        for (int j = 0; j < 4; j++)
            Zh[(size_t)(c0b + ty*4 + i) * DH + tx*4 + j] = accum[i][j] * inv;
    }
}

// ---------------------------------------------------------------------------
// Kernel 3: output projection — R16: 32x64 tiles, 128 threads (4x4 microtile
// per thread, same scalar-LDS inner loop pattern). 1024 blocks -> 6.92
// tile-units/SM, killing the 15.6% wave-quantization loss of the 512-block
// version.
// ---------------------------------------------------------------------------
__global__ __launch_bounds__(128) void oproj_kernel(
    const float* __restrict__ wo, float* __restrict__ out)
{
    __shared__ float As[32][33];
    __shared__ float Bs[64][33];

    const int e0 = blockIdx.x * 64;
    const int c0 = blockIdx.y * 32;
    const int tx = threadIdx.x;          // 0..15 -> n
    const int ty = threadIdx.y;          // 0..7  -> m
    const int t  = ty * 16 + tx;

    float acc[4][4] = {};

    for (int k0 = 0; k0 < NH * DH; k0 += 32) {
        // A tile: 32 rows x 32 k = 256 float4; 2 per thread.
        #pragma unroll
        for (int i = 0; i < 2; i++) {
            int f = t + 128 * i;
            int row = f >> 3, quad = f & 7;
            int k = k0 + quad * 4;
            int a = k >> 6, h = k & 63;
            float4 av = *(const float4*)(g_z + (size_t)a * SEQ * DH + (size_t)(c0 + row) * DH + h);
            As[row][quad*4+0] = av.x; As[row][quad*4+1] = av.y;
            As[row][quad*4+2] = av.z; As[row][quad*4+3] = av.w;
        }
        // B tile: 64 rows x 32 k = 512 float4; 4 per thread.
        #pragma unroll
        for (int i = 0; i < 4; i++) {
            int f = t + 128 * i;
            int row = f >> 3, quad = f & 7;
            int k = k0 + quad * 4;
            int a = k >> 6, h = k & 63;
            float4 bv = *(const float4*)(wo + (size_t)a * DE * DH + (size_t)(e0 + row) * DH + h);
            Bs[row][quad*4+0] = bv.x; Bs[row][quad*4+1] = bv.y;
            Bs[row][quad*4+2] = bv.z; Bs[row][quad*4+3] = bv.w;
        }
        __syncthreads();

        #pragma unroll
        for (int kk = 0; kk < 32; kk++) {
            float a[4], b[4];
            #pragma unroll
            for (int i = 0; i < 4; i++) a[i] = As[ty*4 + i][kk];
            #pragma unroll
            for (int j = 0; j < 4; j++) b[j] = Bs[tx*4 + j][kk];
            #pragma unroll
            for (int i = 0; i < 4; i++)
                #pragma unroll
                for (int j = 0; j < 4; j++)
                    acc[i][j] = fmaf(a[i], b[j], acc[i][j]);
        }
        __syncthreads();
    }

    #pragma unroll
    for (int i = 0; i < 4; i++)
        #pragma unroll
        for (int j = 0; j < 4; j++)
            out[(size_t)(c0 + ty*4 + i) * DE + e0 + tx*4 + j] = acc[i][j];
}

// ---------------------------------------------------------------------------
extern "C" void kernel_launch(void* const* d_in, const int* in_sizes, int n_in,
                              void* d_out, int out_size)
{
    const float* x  = (const float*)d_in[0];
    const float* wq = (const float*)d_in[1];
    const float* wk = (const float*)d_in[2];
    const float* wv = (const float*)d_in[3];
    const float* wo = (const float*)d_in[4];
    float* out = (float*)d_out;

    dim3 blk(16, 16);

    qkv_kernel<<<dim3(1, SEQ / 64, 48), blk>>>(x, wq, wk, wv);

    // LPT schedule over SM residue classes (bid % 148 shares an SM).
    Sched sched;
    {
        int load[148], cnt[148];
        for (int r = 0; r < 148; r++) { load[r] = 0; cnt[r] = 0; }
        for (int s = 32; s >= 1; s--) {
            for (int head = 0; head < NH; head++) {
                int best = -1;
                for (int r = 0; r < 148; r++) {
                    int slots = (r < 68) ? 4 : 3;
                    if (cnt[r] < slots && (best < 0 || load[r] < load[best]))
                        best = r;
                }
                int bid = best + 148 * cnt[best];
                cnt[best]++;
                load[best] += s;
                sched.m[bid] = (short)(head * 32 + (s - 1));
            }
        }
    }

    const size_t shm = 4 * 64 * FST * sizeof(float);  // 69632 B
    cudaFuncSetAttribute(flash_kernel, cudaFuncAttributeMaxDynamicSharedMemorySize, (int)shm);
    flash_kernel<<<512, blk, shm>>>(sched);

    oproj_kernel<<<dim3(DE / 64, SEQ / 32), dim3(16, 8)>>>(wo, out);
}